// round 10
// baseline (speedup 1.0000x reference)
#include <cuda_runtime.h>

// DeepSeek-V3 top-k router. TWO tokens per warp (one per 16-lane half).
// All selection math in order-preserving uint key domain (IMNMX/ISETP).
// Lane hl owns experts 16hl..16hl+15; group g = lane pair {2g,2g+1}.
// Extraction: redux.max for winner value, redux.min on expert index for
// winner location (exact lowest-index tie-break), no ballots/shfls in loop.
// Output: d_out[0..T*8) = indices (float), d_out[T*8..2*T*8) = weights.

#define FULLM 0xffffffffu

static __device__ __forceinline__ unsigned f2ou(float f) {
    unsigned u = __float_as_uint(f);
    return u ^ ((unsigned)((int)u >> 31) | 0x80000000u);
}
static __device__ __forceinline__ float ou2f(unsigned k) {
    unsigned m = (unsigned)((int)k >> 31);
    return __uint_as_float(k ^ ((m & 0x80000000u) | ~m));
}
static __device__ __forceinline__ float sigf(float x) {
    return __fdividef(1.0f, 1.0f + __expf(-x));
}

__global__ __launch_bounds__(128) void deepseek_router_kernel(
    const float* __restrict__ logits,
    const float* __restrict__ bias,
    float* __restrict__ out_idx,
    float* __restrict__ out_w,
    int T)
{
    int warp = (int)((blockIdx.x * blockDim.x + threadIdx.x) >> 5);
    int lane = threadIdx.x & 31;
    int half = lane >> 4;
    int hl   = lane & 15;
    unsigned halfmask = 0xffffu << (half * 16);

    int token = warp * 2 + half;
    if (token >= T) token = T - 1;     // tail: duplicate work, identical writes

    // ---- phase A: load 16 experts/lane, corrected scores -> uint keys
    const float4* row4 = (const float4*)(logits + (long long)token * 256);
    const float4* b4   = (const float4*)bias;
    unsigned key[16];
    #pragma unroll
    for (int j = 0; j < 4; j++) {
        float4 x = __ldg(row4 + hl * 4 + j);
        float4 b = __ldg(b4   + hl * 4 + j);
        key[j * 4 + 0] = f2ou(sigf(x.x) + b.x);
        key[j * 4 + 1] = f2ou(sigf(x.y) + b.y);
        key[j * 4 + 2] = f2ou(sigf(x.z) + b.z);
        key[j * 4 + 3] = f2ou(sigf(x.w) + b.w);
    }

    // ---- lane-local top-2 over 16 (two ILP chains of 8, then merge)
    unsigned a1 = max(key[0], key[1]), a2 = min(key[0], key[1]);
    unsigned b1 = max(key[8], key[9]), b2 = min(key[8], key[9]);
    #pragma unroll
    for (int i = 2; i < 8; i++) {
        unsigned hiA = max(a1, key[i]);
        a2 = max(a2, min(a1, key[i]));  a1 = hiA;
        unsigned hiB = max(b1, key[8 + i]);
        b2 = max(b2, min(b1, key[8 + i]));  b1 = hiB;
    }
    unsigned m1 = max(a1, b1);
    unsigned m2 = max(min(a1, b1), max(a2, b2));
    // ---- merge across the lane pair (group = 2 lanes)
    {
        unsigned o1 = __shfl_xor_sync(FULLM, m1, 1);
        unsigned o2 = __shfl_xor_sync(FULLM, m2, 1);
        unsigned n1 = max(m1, o1);
        m2 = max(min(m1, o1), max(m2, o2));
        m1 = n1;
    }
    float gs = ou2f(m1) + ou2f(m2);    // group score (replicated in pair)

    // ---- rank via index-folded key: exact value order, lower-index ties win
    int grp = hl >> 1;
    unsigned gk = (f2ou(gs) & ~7u) | (7u - (unsigned)grp);
    int rank = 0;
    #pragma unroll
    for (int e = 1; e < 8; e++) {
        unsigned ok = __shfl_xor_sync(FULLM, gk, e * 2);  // stride<=14: in-half
        rank += (ok > gk);
    }
    bool sel = rank < 4;

    // ---- compact: 8 active lanes x16 -> 16 lanes x8 (expert order preserved)
    unsigned am = __ballot_sync(FULLM, sel);
    unsigned hm = (am >> (half * 16)) & 0xffffu;         // 8 bits set
    int srcl = (int)__fns(hm, 0, (hl >> 1) + 1);
    int src  = srcl + half * 16;
    bool odd = (hl & 1);
    unsigned kv[8];
    #pragma unroll
    for (int i = 0; i < 8; i++) {
        unsigned uA = __shfl_sync(FULLM, key[i],     src);
        unsigned uB = __shfl_sync(FULLM, key[8 + i], src);
        kv[i] = odd ? uB : uA;
    }
    int ebase = srcl * 16 + (odd ? 8 : 0);               // expert idx of kv[0]

    // ---- iterative top-8 over the 128 live candidates (per half)
    float wsum = 0.0f;
    float myw = 0.0f;
    int   mybi = 0;
    #pragma unroll
    for (int k = 0; k < 8; k++) {
        unsigned lm = max(max(max(kv[0], kv[1]), max(kv[2], kv[3])),
                          max(max(kv[4], kv[5]), max(kv[6], kv[7])));
        unsigned winu = __reduce_max_sync(halfmask, lm);

        int slot = 7;                                    // lowest matching slot
        #pragma unroll
        for (int i = 6; i >= 0; i--) slot = (kv[i] == winu) ? i : slot;
        unsigned cand = (lm == winu) ? (unsigned)(ebase + slot) : 1023u;
        unsigned biu  = __reduce_min_sync(halfmask, cand);  // lowest expert idx
        int bi = (int)biu;
        bool amw = (cand == biu);                        // exactly one lane
        #pragma unroll
        for (int i = 0; i < 8; i++) if (amw && kv[i] == winu) kv[i] = 0u;

        float w = ou2f(winu) - __ldg(bias + bi);         // sigmoid score (+-1 ulp)
        wsum += w;
        if (hl == k) { myw = w; mybi = bi; }
    }

    float inv = 2.5f * __fdividef(1.0f, wsum + 1e-20f);

    if (hl < 8) {                                        // distributed epilogue
        long long base = (long long)token * 8 + hl;
        out_idx[base] = (float)mybi;
        out_w[base]   = myw * inv;
    }
}

extern "C" void kernel_launch(void* const* d_in, const int* in_sizes, int n_in,
                              void* d_out, int out_size)
{
    const float* logits = (const float*)d_in[0];
    const float* bias   = (const float*)d_in[1];
    int T = in_sizes[0] / 256;

    float* out     = (float*)d_out;
    float* out_idx = out;
    float* out_w   = out + (long long)T * 8;

    const int WARPS_PER_BLOCK = 4;                       // 8 tokens per block
    int nwarps = (T + 1) / 2;
    dim3 block(WARPS_PER_BLOCK * 32);
    dim3 grid((nwarps + WARPS_PER_BLOCK - 1) / WARPS_PER_BLOCK);
    deepseek_router_kernel<<<grid, block>>>(logits, bias, out_idx, out_w, T);
}

// round 11
// speedup vs baseline: 1.0867x; 1.0867x over previous
#include <cuda_runtime.h>

// DeepSeek-V3 top-k router. TWO tokens per warp (one per 16-lane half).
// Lane hl owns experts 16hl..16hl+15; group g = lane pair {2g,2g+1}.
// Float domain through top-2/rank/compaction (FMNMX, exact); order-preserving
// uint keys only for the 8 compacted candidates. Extraction loop keeps the
// slot-scan and index shfl OFF the inter-iteration dependency chain:
//   redux.max -> setp -> ballot -> ffs -> clear   (critical path)
//   slot-scan, shfl(index), bias LDG, weight      (off path)
// Output: d_out[0..T*8) = indices (float), d_out[T*8..2*T*8) = weights.

#define FULLM 0xffffffffu

static __device__ __forceinline__ unsigned f2ou(float f) {
    unsigned u = __float_as_uint(f);
    return u ^ ((unsigned)((int)u >> 31) | 0x80000000u);
}
static __device__ __forceinline__ float ou2f(unsigned k) {
    unsigned m = (unsigned)((int)k >> 31);
    return __uint_as_float(k ^ ((m & 0x80000000u) | ~m));
}
static __device__ __forceinline__ float sigf(float x) {
    return __fdividef(1.0f, 1.0f + __expf(-x));
}

__global__ __launch_bounds__(256) void deepseek_router_kernel(
    const float* __restrict__ logits,
    const float* __restrict__ bias,
    float* __restrict__ out_idx,
    float* __restrict__ out_w,
    int T)
{
    int warp = (int)((blockIdx.x * blockDim.x + threadIdx.x) >> 5);
    int lane = threadIdx.x & 31;
    int half = lane >> 4;
    int hl   = lane & 15;
    unsigned halfmask = 0xffffu << (half * 16);

    int token = warp * 2 + half;
    if (token >= T) token = T - 1;     // tail: duplicate work, identical writes

    // ---- phase A: 16 experts/lane, corrected scores (float)
    const float4* row4 = (const float4*)(logits + (long long)token * 256);
    const float4* b4   = (const float4*)bias;
    float c[16];
    #pragma unroll
    for (int j = 0; j < 4; j++) {
        float4 x = __ldg(row4 + hl * 4 + j);
        float4 b = __ldg(b4   + hl * 4 + j);
        c[j * 4 + 0] = sigf(x.x) + b.x;
        c[j * 4 + 1] = sigf(x.y) + b.y;
        c[j * 4 + 2] = sigf(x.z) + b.z;
        c[j * 4 + 3] = sigf(x.w) + b.w;
    }

    // ---- lane-local top-2 over 16 (two ILP chains of 8, then merge)
    float a1 = fmaxf(c[0], c[1]), a2 = fminf(c[0], c[1]);
    float b1 = fmaxf(c[8], c[9]), b2 = fminf(c[8], c[9]);
    #pragma unroll
    for (int i = 2; i < 8; i++) {
        float hiA = fmaxf(a1, c[i]);
        a2 = fmaxf(a2, fminf(a1, c[i]));  a1 = hiA;
        float hiB = fmaxf(b1, c[8 + i]);
        b2 = fmaxf(b2, fminf(b1, c[8 + i]));  b1 = hiB;
    }
    float m1 = fmaxf(a1, b1);
    float m2 = fmaxf(fminf(a1, b1), fmaxf(a2, b2));
    // ---- merge across the lane pair (group = 2 lanes)
    {
        float o1 = __shfl_xor_sync(FULLM, m1, 1);
        float o2 = __shfl_xor_sync(FULLM, m2, 1);
        float n1 = fmaxf(m1, o1);
        m2 = fmaxf(fminf(m1, o1), fmaxf(m2, o2));
        m1 = n1;
    }
    float gs = m1 + m2;                // group score (replicated in pair)

    // ---- rank via index-folded key: exact value order, lower-index ties win
    int grp = hl >> 1;
    unsigned gk = (f2ou(gs) & ~7u) | (7u - (unsigned)grp);
    int rank = 0;
    #pragma unroll
    for (int e = 1; e < 8; e++) {
        unsigned ok = __shfl_xor_sync(FULLM, gk, e * 2);  // stride<=14: in-half
        rank += (ok > gk);
    }
    bool sel = rank < 4;

    // ---- compact: 8 active lanes x16 -> 16 lanes x8 (expert order preserved)
    unsigned am = __ballot_sync(FULLM, sel);
    unsigned hm = (am >> (half * 16)) & 0xffffu;          // 8 bits set
    int srcl = (int)__fns(hm, 0, (hl >> 1) + 1);
    int src  = srcl + half * 16;
    bool odd = (hl & 1);
    unsigned kv[8];
    #pragma unroll
    for (int i = 0; i < 8; i++) {
        float rA = __shfl_sync(FULLM, c[i],     src);
        float rB = __shfl_sync(FULLM, c[8 + i], src);
        kv[i] = f2ou(odd ? rB : rA);                      // convert only 8
    }
    int ebase = srcl * 16 + (odd ? 8 : 0);                // expert idx of kv[0]

    // ---- iterative top-8 over the 128 live candidates (per half)
    float wsum = 0.0f;
    float myw = 0.0f;
    int   mybi = 0;
    #pragma unroll
    for (int k = 0; k < 8; k++) {
        unsigned lm = max(max(max(kv[0], kv[1]), max(kv[2], kv[3])),
                          max(max(kv[4], kv[5]), max(kv[6], kv[7])));
        unsigned winu = __reduce_max_sync(halfmask, lm);
        unsigned bal  = __ballot_sync(halfmask, lm == winu);
        int wl = __ffs((int)bal) - 1;                     // lowest lane wins ties
        bool amw = (lane == wl);

        // off-critical-path: locate slot, recover index, weight
        int slot = 7;
        #pragma unroll
        for (int i = 6; i >= 0; i--) slot = (kv[i] == winu) ? i : slot;
        // critical path: clear exactly the winner lane's matching slot(s)
        #pragma unroll
        for (int i = 0; i < 8; i++) if (amw && kv[i] == winu) kv[i] = 0u;

        int myidx = ebase + slot;
        int bi = __shfl_sync(FULLM, myidx, wl);           // uniform per half

        float w = ou2f(winu) - __ldg(bias + bi);          // sigmoid score (+-1 ulp)
        wsum += w;
        if (hl == k) { myw = w; mybi = bi; }
    }

    float inv = 2.5f * __fdividef(1.0f, wsum + 1e-20f);

    if (hl < 8) {                                         // distributed epilogue
        long long base = (long long)token * 8 + hl;
        out_idx[base] = (float)mybi;
        out_w[base]   = myw * inv;
    }
}

extern "C" void kernel_launch(void* const* d_in, const int* in_sizes, int n_in,
                              void* d_out, int out_size)
{
    const float* logits = (const float*)d_in[0];
    const float* bias   = (const float*)d_in[1];
    int T = in_sizes[0] / 256;

    float* out     = (float*)d_out;
    float* out_idx = out;
    float* out_w   = out + (long long)T * 8;

    const int WARPS_PER_BLOCK = 8;                        // 16 tokens per block
    int nwarps = (T + 1) / 2;
    dim3 block(WARPS_PER_BLOCK * 32);
    dim3 grid((nwarps + WARPS_PER_BLOCK - 1) / WARPS_PER_BLOCK);
    deepseek_router_kernel<<<grid, block>>>(logits, bias, out_idx, out_w, T);
}